// round 14
// baseline (speedup 1.0000x reference)
#include <cuda_runtime.h>
#include <cuda_fp16.h>
#include <mma.h>
#include <cstdint>

using namespace nvcuda;

#define N_NODES 50000
#define N_EDGES 800000
#define E_TOT   (N_EDGES + N_NODES)   // 850000 (self-loops appended)
#define IN_CH   128
#define HC      128                    // HEADS*OUT_CH
#define HEADS   2
#define OUT_CH  64
#define NEG_SLOPE 0.2f

#define SCAN_B  256
#define SCAN_NB ((N_NODES + SCAN_B - 1) / SCAN_B)   // 196
#define GEMM1_BLOCKS ((N_NODES + 63) / 64)          // 782
#define COUNT_BLOCKS ((N_EDGES / 4 + 255) / 256)    // 782

// ---------------- scratch (static device memory; no allocations) -------------
__device__ uint2  g_xhh[N_NODES * 32];          // fp16 xh [N][64 x half2] (256B/row)
__device__ float2 g_al2[N_NODES];               // (alpha_l h0, h1) per node
__device__ float2 g_ar2[N_NODES];               // (alpha_r h0, h1) per node
__device__ int    g_cnt[N_NODES];               // zero-init; delta counts (self-loop implicit)
__device__ int    g_ptr[N_NODES + 1];           // CSR row pointers
__device__ int    g_rank[N_EDGES];              // per-edge rank within its dst
__device__ int    g_srcs[E_TOT];                // CSR: src node per slot
__device__ int    g_bsum[SCAN_NB];              // per-block scan totals

__device__ __forceinline__ float leaky(float v) {
    return v > 0.0f ? v : NEG_SLOPE * v;
}

// smem layout for GEMM1 role (A/B tiles aliased by the C staging buffer)
#define AS_STRIDE 72      // halfs per A row (64 + pad), 144B
#define BS_STRIDE 136     // halfs per B row (128 + pad), 272B
#define CS_STRIDE 132     // floats per C row (128 + pad), 528B
#define AS_BYTES  (64 * AS_STRIDE * 2)                 // 9216
#define AB_BYTES  (AS_BYTES + 64 * BS_STRIDE * 2)      // 26624
#define CS_BYTES  (64 * CS_STRIDE * 4)                 // 33792
#define SMEM_BYTES (CS_BYTES > AB_BYTES ? CS_BYTES : AB_BYTES)

// ========== MEGA1: [GEMM1(wmma fp16) blocks | edge-count blocks] =============
__global__ void k_mega1(const float* __restrict__ x,
                        const float* __restrict__ Wl,
                        const float* __restrict__ att_l,
                        const float* __restrict__ att_r,
                        const int*   __restrict__ ei) {
    __shared__ __align__(16) char smem_raw[SMEM_BYTES];

    const int tid = threadIdx.x;

    if (blockIdx.x >= GEMM1_BLOCKS) {
        // ---- histogram role: 4 edges/thread, record ranks ----
        int t = (blockIdx.x - GEMM1_BLOCKS) * 256 + tid;
        if (t < N_EDGES / 4) {
            int4 d = ((const int4*)(ei + N_EDGES))[t];
            int4 r = make_int4(0, 0, 0, 0);
            if ((unsigned)d.x < N_NODES) r.x = atomicAdd(&g_cnt[d.x], 1);
            if ((unsigned)d.y < N_NODES) r.y = atomicAdd(&g_cnt[d.y], 1);
            if ((unsigned)d.z < N_NODES) r.z = atomicAdd(&g_cnt[d.z], 1);
            if ((unsigned)d.w < N_NODES) r.w = atomicAdd(&g_cnt[d.w], 1);
            ((int4*)g_rank)[t] = r;
        }
        return;
    }

    // ---- GEMM role: xh = x @ Wl via wmma fp16 (fp32 accum) ----
    __half (*As)[AS_STRIDE] = reinterpret_cast<__half(*)[AS_STRIDE]>(smem_raw);
    __half (*Bs)[BS_STRIDE] = reinterpret_cast<__half(*)[BS_STRIDE]>(smem_raw + AS_BYTES);
    float  (*Cs)[CS_STRIDE] = reinterpret_cast<float(*)[CS_STRIDE]>(smem_raw);

    const int row0 = blockIdx.x * 64;
    const int wid  = tid >> 5;            // 0..7
    const int wr   = wid >> 2;            // 0..1 -> 32-row tile
    const int wc   = wid & 3;             // 0..3 -> 32-col tile

    wmma::fragment<wmma::accumulator, 16, 16, 16, float> cfrag[2][2];
#pragma unroll
    for (int i = 0; i < 2; i++)
#pragma unroll
        for (int j = 0; j < 2; j++) wmma::fill_fragment(cfrag[i][j], 0.0f);

    const float4* x4  = (const float4*)x;
    const float4* Wl4 = (const float4*)Wl;

    for (int k0 = 0; k0 < IN_CH; k0 += 64) {
        __syncthreads();
        {
            int r  = tid >> 2;
            int cs = (tid & 3) * 16;
            int grow = row0 + r;
            __half2* dst = (__half2*)&As[r][cs];
#pragma unroll
            for (int u = 0; u < 4; u++) {
                float4 f = make_float4(0.f, 0.f, 0.f, 0.f);
                if (grow < N_NODES)
                    f = x4[(size_t)grow * (IN_CH / 4) + (k0 + cs) / 4 + u];
                dst[2 * u]     = __floats2half2_rn(f.x, f.y);
                dst[2 * u + 1] = __floats2half2_rn(f.z, f.w);
            }
        }
        {
            int kr = tid >> 2;
            int bc = (tid & 3) * 32;
            __half2* dst = (__half2*)&Bs[kr][bc];
#pragma unroll
            for (int u = 0; u < 8; u++) {
                float4 f = Wl4[(size_t)(k0 + kr) * (HC / 4) + bc / 4 + u];
                dst[2 * u]     = __floats2half2_rn(f.x, f.y);
                dst[2 * u + 1] = __floats2half2_rn(f.z, f.w);
            }
        }
        __syncthreads();
#pragma unroll
        for (int ks = 0; ks < 4; ks++) {
            wmma::fragment<wmma::matrix_a, 16, 16, 16, __half, wmma::row_major> afrag[2];
            wmma::fragment<wmma::matrix_b, 16, 16, 16, __half, wmma::row_major> bfrag[2];
#pragma unroll
            for (int i = 0; i < 2; i++)
                wmma::load_matrix_sync(afrag[i], &As[wr * 32 + i * 16][ks * 16], AS_STRIDE);
#pragma unroll
            for (int j = 0; j < 2; j++)
                wmma::load_matrix_sync(bfrag[j], &Bs[ks * 16][wc * 32 + j * 16], BS_STRIDE);
#pragma unroll
            for (int i = 0; i < 2; i++)
#pragma unroll
                for (int j = 0; j < 2; j++)
                    wmma::mma_sync(cfrag[i][j], afrag[i], bfrag[j], cfrag[i][j]);
        }
    }
    __syncthreads();
#pragma unroll
    for (int i = 0; i < 2; i++)
#pragma unroll
        for (int j = 0; j < 2; j++)
            wmma::store_matrix_sync(&Cs[wr * 32 + i * 16][wc * 32 + j * 16],
                                    cfrag[i][j], CS_STRIDE, wmma::mem_row_major);
    __syncthreads();

    // epilogue: fp16 xh store + fused attention dots
    const int tn = tid & 31;
    const int tm = tid >> 5;
    float4 attl = ((const float4*)att_l)[tn];
    float4 attr = ((const float4*)att_r)[tn];
#pragma unroll
    for (int i = 0; i < 8; i++) {
        int row = tm * 8 + i;
        float4 v = *(float4*)&Cs[row][tn * 4];

        float pl = v.x * attl.x + v.y * attl.y + v.z * attl.z + v.w * attl.w;
        float pr = v.x * attr.x + v.y * attr.y + v.z * attr.z + v.w * attr.w;
#pragma unroll
        for (int off = 8; off; off >>= 1) {
            pl += __shfl_xor_sync(0xffffffffu, pl, off);
            pr += __shfl_xor_sync(0xffffffffu, pr, off);
        }
        float pl1 = __shfl_sync(0xffffffffu, pl, 16);
        float pr1 = __shfl_sync(0xffffffffu, pr, 16);

        int grow = row0 + row;
        if (grow < N_NODES) {
            __half2 h01 = __floats2half2_rn(v.x, v.y);
            __half2 h23 = __floats2half2_rn(v.z, v.w);
            uint2 pk;
            pk.x = *reinterpret_cast<unsigned*>(&h01);
            pk.y = *reinterpret_cast<unsigned*>(&h23);
            g_xhh[(size_t)grow * 32 + tn] = pk;
            if (tn == 0) {
                g_al2[grow] = make_float2(pl, pl1);
                g_ar2[grow] = make_float2(pr, pr1);
            }
        }
    }
}

// Phase A: per-block scan of (cnt+1); resets cnt for the next graph replay.
__global__ void k_scan_a() {
    __shared__ int sm[SCAN_B];
    const int tid = threadIdx.x;
    const int idx = blockIdx.x * SCAN_B + tid;
    int v = 0;
    if (idx < N_NODES) {
        v = g_cnt[idx] + 1;      // +1 = self-loop (occupies LAST slot of row)
        g_cnt[idx] = 0;          // re-arm for next replay
    }
    sm[tid] = v;
    __syncthreads();
#pragma unroll
    for (int off = 1; off < SCAN_B; off <<= 1) {
        int t = 0;
        if (tid >= off) t = sm[tid - off];
        __syncthreads();
        sm[tid] += t;
        __syncthreads();
    }
    if (idx < N_NODES) g_ptr[idx] = sm[tid] - v;       // local exclusive
    if (tid == SCAN_B - 1) g_bsum[blockIdx.x] = sm[tid];
}

// Phase BC: each block reduces bsum[0..blk-1] itself, then applies offset.
__global__ void k_scan_bc() {
    __shared__ int red[SCAN_B];
    const int tid = threadIdx.x;
    const int b   = blockIdx.x;
    red[tid] = (tid < SCAN_NB && tid < b) ? g_bsum[tid] : 0;
    __syncthreads();
#pragma unroll
    for (int off = SCAN_B / 2; off; off >>= 1) {
        if (tid < off) red[tid] += red[tid + off];
        __syncthreads();
    }
    const int off0 = red[0];
    const int idx = b * SCAN_B + tid;
    if (idx < N_NODES)
        g_ptr[idx] += off0;
    if (b == SCAN_NB - 1 && tid == 0)
        g_ptr[N_NODES] = off0 + g_bsum[SCAN_NB - 1];
}

// ============ scatter: ATOMIC-FREE via precomputed ranks =====================
__global__ void k_scatter(const int* __restrict__ ei) {
    const int NE4 = N_EDGES / 4;
    int t = blockIdx.x * blockDim.x + threadIdx.x;
    if (t < NE4) {
        int4 s = ((const int4*)ei)[t];
        int4 d = ((const int4*)(ei + N_EDGES))[t];
        int4 r = ((const int4*)g_rank)[t];
        if ((unsigned)s.x < N_NODES && (unsigned)d.x < N_NODES)
            g_srcs[g_ptr[d.x] + r.x] = s.x;
        if ((unsigned)s.y < N_NODES && (unsigned)d.y < N_NODES)
            g_srcs[g_ptr[d.y] + r.y] = s.y;
        if ((unsigned)s.z < N_NODES && (unsigned)d.z < N_NODES)
            g_srcs[g_ptr[d.z] + r.z] = s.z;
        if ((unsigned)s.w < N_NODES && (unsigned)d.w < N_NODES)
            g_srcs[g_ptr[d.w] + r.w] = s.w;
    } else {
        int n = t - NE4;
        if (n < N_NODES)
            g_srcs[g_ptr[n + 1] - 1] = n;     // self-loop: last slot of row n
    }
}

// ========= FUSED: aggregate (8 nodes/warp -> smem) + wmma GEMM2 ==============
// Block = 256 threads = 8 warps; block covers 64 nodes. Each warp runs the
// single-pass softmax-gather for its 8 nodes, storing fp16 rows directly into
// the GEMM A-tile in smem. Then the block does out = AggS @ Wout + bias.
#define G2_A_STRIDE 136   // halfs per agg row (128 + 8 pad), 272B
#define G2_B_STRIDE 72    // halfs per Wout row (64 + 8 pad), 144B
#define G2_C_STRIDE 68    // floats per C row (64 + 4 pad), 272B

__global__ __launch_bounds__(256) void k_agg_out(const float* __restrict__ Wout,
                                                 const float* __restrict__ bias,
                                                 float* __restrict__ out) {
    __shared__ __align__(16) __half AggS[64][G2_A_STRIDE];   // aliased by Cs
    __shared__ __align__(16) __half WtS[128][G2_B_STRIDE];
    __shared__ float4 meta[8][32];
    float (*Cs)[G2_C_STRIDE] = reinterpret_cast<float(*)[G2_C_STRIDE]>(&AggS[0][0]);

    const int tid  = threadIdx.x;
    const int wrp  = tid >> 5;
    const int lane = tid & 31;
    const int row0 = blockIdx.x * 64;
    const int h    = (lane >= 16) ? 1 : 0;

    // load Wout (fp32 -> fp16) while aggregation proceeds afterwards
    const float4* W4 = (const float4*)Wout;
#pragma unroll
    for (int it = 0; it < 8; it++) {
        int idx = tid + it * 256;            // 0..2047 float4s
        int r = idx >> 4, c4 = idx & 15;
        float4 f = W4[r * 16 + c4];
        __half2* dst = (__half2*)&WtS[r][c4 * 4];
        dst[0] = __floats2half2_rn(f.x, f.y);
        dst[1] = __floats2half2_rn(f.z, f.w);
    }

    // ---- aggregate 8 nodes per warp (single-pass softmax) ----
#pragma unroll 1
    for (int it = 0; it < 8; it++) {
        const int row = wrp * 8 + it;
        const int node = row0 + row;
        uint2 pk = make_uint2(0u, 0u);
        if (node < N_NODES) {
            const int start = g_ptr[node], end = g_ptr[node + 1];
            const float2 ar = g_ar2[node];
            float sum0 = 0.f, sum1 = 0.f;
            float4 acc = make_float4(0.f, 0.f, 0.f, 0.f);

            for (int eb = start; eb < end; eb += 32) {
                int e = eb + lane;
                float w0 = 0.f, w1 = 0.f;
                int sm_ = 0;
                if (e < end) {
                    sm_ = g_srcs[e];
                    float2 al = g_al2[sm_];
                    w0 = __expf(leaky(al.x + ar.x));
                    w1 = __expf(leaky(al.y + ar.y));
                    sum0 += w0;
                    sum1 += w1;
                }
                meta[wrp][lane] = make_float4(__int_as_float(sm_), w0, w1, 0.f);
                __syncwarp();
                const int cnt = min(32, end - eb);
                const float4* mrow = meta[wrp];

                int j = 0;
                for (; j + 8 <= cnt; j += 8) {
                    uint2 p[8];
                    float wj[8];
#pragma unroll
                    for (int u = 0; u < 8; u++) {
                        float4 mt = mrow[j + u];
                        wj[u] = h ? mt.z : mt.y;
                        p[u] = g_xhh[(size_t)__float_as_int(mt.x) * 32 + lane];
                    }
#pragma unroll
                    for (int u = 0; u < 8; u++) {
                        __half2 h01 = *reinterpret_cast<__half2*>(&p[u].x);
                        __half2 h23 = *reinterpret_cast<__half2*>(&p[u].y);
                        float2 f01 = __half22float2(h01);
                        float2 f23 = __half22float2(h23);
                        acc.x += wj[u] * f01.x; acc.y += wj[u] * f01.y;
                        acc.z += wj[u] * f23.x; acc.w += wj[u] * f23.y;
                    }
                }
                for (; j < cnt; j++) {
                    float4 mt = mrow[j];
                    float wj = h ? mt.z : mt.y;
                    uint2 p = g_xhh[(size_t)__float_as_int(mt.x) * 32 + lane];
                    __half2 h01 = *reinterpret_cast<__half2*>(&p.x);
                    __half2 h23 = *reinterpret_cast<__half2*>(&p.y);
                    float2 f01 = __half22float2(h01);
                    float2 f23 = __half22float2(h23);
                    acc.x += wj * f01.x; acc.y += wj * f01.y;
                    acc.z += wj * f23.x; acc.w += wj * f23.y;
                }
                __syncwarp();
            }

#pragma unroll
            for (int off = 16; off; off >>= 1) {
                sum0 += __shfl_xor_sync(0xffffffffu, sum0, off);
                sum1 += __shfl_xor_sync(0xffffffffu, sum1, off);
            }
            const float inv = 1.0f / ((h ? sum1 : sum0) + 1e-16f);
            __half2 a01 = __floats2half2_rn(acc.x * inv, acc.y * inv);
            __half2 a23 = __floats2half2_rn(acc.z * inv, acc.w * inv);
            pk.x = *reinterpret_cast<unsigned*>(&a01);
            pk.y = *reinterpret_cast<unsigned*>(&a23);
        }
        *(uint2*)&AggS[row][lane * 4] = pk;   // fp16 row into GEMM A-tile
    }
    __syncthreads();

    // ---- wmma GEMM2: Cs = AggS @ WtS ----
    const int wr = wrp >> 2;     // 0..1 -> 32-row tile
    const int wc = wrp & 3;      // 0..3 -> 16-col tile

    wmma::fragment<wmma::accumulator, 16, 16, 16, float> cfrag[2];
#pragma unroll
    for (int i = 0; i < 2; i++) wmma::fill_fragment(cfrag[i], 0.0f);

#pragma unroll
    for (int ks = 0; ks < 8; ks++) {
        wmma::fragment<wmma::matrix_a, 16, 16, 16, __half, wmma::row_major> afrag[2];
        wmma::fragment<wmma::matrix_b, 16, 16, 16, __half, wmma::row_major> bfrag;
#pragma unroll
        for (int i = 0; i < 2; i++)
            wmma::load_matrix_sync(afrag[i], &AggS[wr * 32 + i * 16][ks * 16], G2_A_STRIDE);
        wmma::load_matrix_sync(bfrag, &WtS[ks * 16][wc * 16], G2_B_STRIDE);
#pragma unroll
        for (int i = 0; i < 2; i++)
            wmma::mma_sync(cfrag[i], afrag[i], bfrag, cfrag[i]);
    }
    __syncthreads();   // done reading AggS; Cs aliases it
#pragma unroll
    for (int i = 0; i < 2; i++)
        wmma::store_matrix_sync(&Cs[wr * 32 + i * 16][wc * 16],
                                cfrag[i], G2_C_STRIDE, wmma::mem_row_major);
    __syncthreads();

    // ---- epilogue: bias add + float4 store ----
    const int tn = tid & 15;
    const int tm = tid >> 4;
    float4 bv = ((const float4*)bias)[tn];
    float4* out4 = (float4*)out;
#pragma unroll
    for (int i = 0; i < 4; i++) {
        int row = tm * 4 + i;
        int grow = row0 + row;
        if (grow < N_NODES) {
            float4 v = *(float4*)&Cs[row][tn * 4];
            v.x += bv.x; v.y += bv.y; v.z += bv.z; v.w += bv.w;
            out4[(size_t)grow * (OUT_CH / 4) + tn] = v;
        }
    }
}

// ============================== launch ======================================
extern "C" void kernel_launch(void* const* d_in, const int* in_sizes, int n_in,
                              void* d_out, int out_size) {
    const float* x     = (const float*)d_in[0];
    const int*   ei    = (const int*)d_in[1];     // int32 edge_index
    const float* Wl    = (const float*)d_in[2];
    const float* att_l = (const float*)d_in[3];
    const float* att_r = (const float*)d_in[4];
    const float* Wout  = (const float*)d_in[5];
    const float* bias  = (const float*)d_in[6];
    float*       out   = (float*)d_out;

    (void)in_sizes; (void)n_in; (void)out_size;

    k_mega1<<<GEMM1_BLOCKS + COUNT_BLOCKS, 256>>>(x, Wl, att_l, att_r, ei);
    k_scan_a<<<SCAN_NB, SCAN_B>>>();
    k_scan_bc<<<SCAN_NB, SCAN_B>>>();
    k_scatter<<<(N_EDGES / 4 + N_NODES + 255) / 256, 256>>>(ei);
    k_agg_out<<<(N_NODES + 63) / 64, 256>>>(Wout, bias, out);
}

// round 15
// speedup vs baseline: 1.0734x; 1.0734x over previous
#include <cuda_runtime.h>
#include <cuda_fp16.h>
#include <mma.h>
#include <cstdint>

using namespace nvcuda;

#define N_NODES 50000
#define N_EDGES 800000
#define E_TOT   (N_EDGES + N_NODES)   // 850000 (self-loops appended)
#define IN_CH   128
#define HC      128                    // HEADS*OUT_CH
#define HEADS   2
#define OUT_CH  64
#define NEG_SLOPE 0.2f

#define SCAN_B  256
#define SCAN_NB ((N_NODES + SCAN_B - 1) / SCAN_B)   // 196
#define GEMM1_BLOCKS ((N_NODES + 63) / 64)          // 782
#define COUNT_BLOCKS ((N_EDGES / 4 + 255) / 256)    // 782

// ---------------- scratch (static device memory; no allocations) -------------
__device__ uint2  g_xhh[N_NODES * 32];          // fp16 xh  [N][64 x half2] (256B/row)
__device__ uint2  g_agghh[N_NODES * 32];        // fp16 agg [N][64 x half2] (256B/row)
__device__ float2 g_al2[N_NODES];               // (alpha_l h0, h1) per node
__device__ float2 g_ar2[N_NODES];               // (alpha_r h0, h1) per node
__device__ int    g_cnt[N_NODES];               // zero-init; delta counts (self-loop implicit)
__device__ int    g_ptr[N_NODES + 1];           // CSR row pointers
__device__ int    g_rank[N_EDGES];              // per-edge rank within its dst
__device__ int    g_srcs[E_TOT];                // CSR: src node per slot
__device__ int    g_bsum[SCAN_NB];              // per-block scan totals

__device__ __forceinline__ float leaky(float v) {
    return v > 0.0f ? v : NEG_SLOPE * v;
}

// smem layout for GEMM1 (A/B tiles aliased by the C staging buffer)
#define AS_STRIDE 72      // halfs per A row (64 + pad), 144B
#define BS_STRIDE 136     // halfs per B row (128 + pad), 272B
#define CS_STRIDE 132     // floats per C row (128 + pad), 528B
#define AS_BYTES  (64 * AS_STRIDE * 2)                 // 9216
#define AB_BYTES  (AS_BYTES + 64 * BS_STRIDE * 2)      // 26624
#define CS_BYTES  (64 * CS_STRIDE * 4)                 // 33792
#define SMEM_BYTES (CS_BYTES > AB_BYTES ? CS_BYTES : AB_BYTES)

// ============== GEMM1 (wmma fp16): xh = x @ Wl + fused att dots ==============
__global__ void k_gemm1(const float* __restrict__ x,
                        const float* __restrict__ Wl,
                        const float* __restrict__ att_l,
                        const float* __restrict__ att_r) {
    __shared__ __align__(16) char smem_raw[SMEM_BYTES];
    __half (*As)[AS_STRIDE] = reinterpret_cast<__half(*)[AS_STRIDE]>(smem_raw);
    __half (*Bs)[BS_STRIDE] = reinterpret_cast<__half(*)[BS_STRIDE]>(smem_raw + AS_BYTES);
    float  (*Cs)[CS_STRIDE] = reinterpret_cast<float(*)[CS_STRIDE]>(smem_raw);

    const int tid = threadIdx.x;
    const int row0 = blockIdx.x * 64;
    const int wid  = tid >> 5;            // 0..7
    const int wr   = wid >> 2;            // 0..1 -> 32-row tile
    const int wc   = wid & 3;             // 0..3 -> 32-col tile

    wmma::fragment<wmma::accumulator, 16, 16, 16, float> cfrag[2][2];
#pragma unroll
    for (int i = 0; i < 2; i++)
#pragma unroll
        for (int j = 0; j < 2; j++) wmma::fill_fragment(cfrag[i][j], 0.0f);

    const float4* x4  = (const float4*)x;
    const float4* Wl4 = (const float4*)Wl;

    for (int k0 = 0; k0 < IN_CH; k0 += 64) {
        __syncthreads();
        {
            int r  = tid >> 2;
            int cs = (tid & 3) * 16;
            int grow = row0 + r;
            __half2* dst = (__half2*)&As[r][cs];
#pragma unroll
            for (int u = 0; u < 4; u++) {
                float4 f = make_float4(0.f, 0.f, 0.f, 0.f);
                if (grow < N_NODES)
                    f = x4[(size_t)grow * (IN_CH / 4) + (k0 + cs) / 4 + u];
                dst[2 * u]     = __floats2half2_rn(f.x, f.y);
                dst[2 * u + 1] = __floats2half2_rn(f.z, f.w);
            }
        }
        {
            int kr = tid >> 2;
            int bc = (tid & 3) * 32;
            __half2* dst = (__half2*)&Bs[kr][bc];
#pragma unroll
            for (int u = 0; u < 8; u++) {
                float4 f = Wl4[(size_t)(k0 + kr) * (HC / 4) + bc / 4 + u];
                dst[2 * u]     = __floats2half2_rn(f.x, f.y);
                dst[2 * u + 1] = __floats2half2_rn(f.z, f.w);
            }
        }
        __syncthreads();
#pragma unroll
        for (int ks = 0; ks < 4; ks++) {
            wmma::fragment<wmma::matrix_a, 16, 16, 16, __half, wmma::row_major> afrag[2];
            wmma::fragment<wmma::matrix_b, 16, 16, 16, __half, wmma::row_major> bfrag[2];
#pragma unroll
            for (int i = 0; i < 2; i++)
                wmma::load_matrix_sync(afrag[i], &As[wr * 32 + i * 16][ks * 16], AS_STRIDE);
#pragma unroll
            for (int j = 0; j < 2; j++)
                wmma::load_matrix_sync(bfrag[j], &Bs[ks * 16][wc * 32 + j * 16], BS_STRIDE);
#pragma unroll
            for (int i = 0; i < 2; i++)
#pragma unroll
                for (int j = 0; j < 2; j++)
                    wmma::mma_sync(cfrag[i][j], afrag[i], bfrag[j], cfrag[i][j]);
        }
    }
    __syncthreads();
#pragma unroll
    for (int i = 0; i < 2; i++)
#pragma unroll
        for (int j = 0; j < 2; j++)
            wmma::store_matrix_sync(&Cs[wr * 32 + i * 16][wc * 32 + j * 16],
                                    cfrag[i][j], CS_STRIDE, wmma::mem_row_major);
    __syncthreads();

    // epilogue: fp16 xh store + fused attention dots
    const int tn = tid & 31;
    const int tm = tid >> 5;
    float4 attl = ((const float4*)att_l)[tn];
    float4 attr = ((const float4*)att_r)[tn];
#pragma unroll
    for (int i = 0; i < 8; i++) {
        int row = tm * 8 + i;
        float4 v = *(float4*)&Cs[row][tn * 4];

        float pl = v.x * attl.x + v.y * attl.y + v.z * attl.z + v.w * attl.w;
        float pr = v.x * attr.x + v.y * attr.y + v.z * attr.z + v.w * attr.w;
#pragma unroll
        for (int off = 8; off; off >>= 1) {
            pl += __shfl_xor_sync(0xffffffffu, pl, off);
            pr += __shfl_xor_sync(0xffffffffu, pr, off);
        }
        float pl1 = __shfl_sync(0xffffffffu, pl, 16);
        float pr1 = __shfl_sync(0xffffffffu, pr, 16);

        int grow = row0 + row;
        if (grow < N_NODES) {
            __half2 h01 = __floats2half2_rn(v.x, v.y);
            __half2 h23 = __floats2half2_rn(v.z, v.w);
            uint2 pk;
            pk.x = *reinterpret_cast<unsigned*>(&h01);
            pk.y = *reinterpret_cast<unsigned*>(&h23);
            g_xhh[(size_t)grow * 32 + tn] = pk;
            if (tn == 0) {
                g_al2[grow] = make_float2(pl, pl1);
                g_ar2[grow] = make_float2(pr, pr1);
            }
        }
    }
}

// ============== count: 4 edges/thread, records per-edge ranks ================
__global__ void k_count(const int* __restrict__ ei) {
    int t = blockIdx.x * blockDim.x + threadIdx.x;
    if (t < N_EDGES / 4) {
        int4 d = ((const int4*)(ei + N_EDGES))[t];
        int4 r = make_int4(0, 0, 0, 0);
        if ((unsigned)d.x < N_NODES) r.x = atomicAdd(&g_cnt[d.x], 1);
        if ((unsigned)d.y < N_NODES) r.y = atomicAdd(&g_cnt[d.y], 1);
        if ((unsigned)d.z < N_NODES) r.z = atomicAdd(&g_cnt[d.z], 1);
        if ((unsigned)d.w < N_NODES) r.w = atomicAdd(&g_cnt[d.w], 1);
        ((int4*)g_rank)[t] = r;
    }
}

// Phase A: per-block scan of (cnt+1); resets cnt for the next graph replay.
__global__ void k_scan_a() {
    __shared__ int sm[SCAN_B];
    const int tid = threadIdx.x;
    const int idx = blockIdx.x * SCAN_B + tid;
    int v = 0;
    if (idx < N_NODES) {
        v = g_cnt[idx] + 1;      // +1 = self-loop (occupies LAST slot of row)
        g_cnt[idx] = 0;          // re-arm for next replay
    }
    sm[tid] = v;
    __syncthreads();
#pragma unroll
    for (int off = 1; off < SCAN_B; off <<= 1) {
        int t = 0;
        if (tid >= off) t = sm[tid - off];
        __syncthreads();
        sm[tid] += t;
        __syncthreads();
    }
    if (idx < N_NODES) g_ptr[idx] = sm[tid] - v;       // local exclusive
    if (tid == SCAN_B - 1) g_bsum[blockIdx.x] = sm[tid];
}

// Phase BC: each block reduces bsum[0..blk-1] itself, then applies offset.
__global__ void k_scan_bc() {
    __shared__ int red[SCAN_B];
    const int tid = threadIdx.x;
    const int b   = blockIdx.x;
    red[tid] = (tid < SCAN_NB && tid < b) ? g_bsum[tid] : 0;
    __syncthreads();
#pragma unroll
    for (int off = SCAN_B / 2; off; off >>= 1) {
        if (tid < off) red[tid] += red[tid + off];
        __syncthreads();
    }
    const int off0 = red[0];
    const int idx = b * SCAN_B + tid;
    if (idx < N_NODES)
        g_ptr[idx] += off0;
    if (b == SCAN_NB - 1 && tid == 0)
        g_ptr[N_NODES] = off0 + g_bsum[SCAN_NB - 1];
}

// ============ scatter: ATOMIC-FREE via precomputed ranks =====================
__global__ void k_scatter(const int* __restrict__ ei) {
    const int NE4 = N_EDGES / 4;
    int t = blockIdx.x * blockDim.x + threadIdx.x;
    if (t < NE4) {
        int4 s = ((const int4*)ei)[t];
        int4 d = ((const int4*)(ei + N_EDGES))[t];
        int4 r = ((const int4*)g_rank)[t];
        if ((unsigned)s.x < N_NODES && (unsigned)d.x < N_NODES)
            g_srcs[g_ptr[d.x] + r.x] = s.x;
        if ((unsigned)s.y < N_NODES && (unsigned)d.y < N_NODES)
            g_srcs[g_ptr[d.y] + r.y] = s.y;
        if ((unsigned)s.z < N_NODES && (unsigned)d.z < N_NODES)
            g_srcs[g_ptr[d.z] + r.z] = s.z;
        if ((unsigned)s.w < N_NODES && (unsigned)d.w < N_NODES)
            g_srcs[g_ptr[d.w] + r.w] = s.w;
    } else {
        int n = t - NE4;
        if (n < N_NODES)
            g_srcs[g_ptr[n + 1] - 1] = n;     // self-loop: last slot of row n
    }
}

// ====== single-pass segment softmax + weighted gather (warp per node) ========
__global__ __launch_bounds__(256) void k_aggregate() {
    __shared__ float4 meta[8][32];       // (src, w0, w1, -) per in-flight edge
    const int wrp  = threadIdx.x >> 5;
    const int warp = (blockIdx.x * blockDim.x + threadIdx.x) >> 5;
    const int lane = threadIdx.x & 31;
    if (warp >= N_NODES) return;
    const int i = warp;
    const int start = g_ptr[i], end = g_ptr[i + 1];

    const float2 ar = g_ar2[i];
    const int h = (lane >= 16) ? 1 : 0;

    float sum0 = 0.f, sum1 = 0.f;        // per-lane weight totals
    float4 acc = make_float4(0.f, 0.f, 0.f, 0.f);

    for (int eb = start; eb < end; eb += 32) {
        int e = eb + lane;
        float w0 = 0.f, w1 = 0.f;
        int sm_ = 0;
        if (e < end) {
            sm_ = g_srcs[e];
            float2 al = g_al2[sm_];
            w0 = __expf(leaky(al.x + ar.x));
            w1 = __expf(leaky(al.y + ar.y));
            sum0 += w0;
            sum1 += w1;
        }
        meta[wrp][lane] = make_float4(__int_as_float(sm_), w0, w1, 0.f);
        __syncwarp();
        const int cnt = min(32, end - eb);
        const float4* mrow = meta[wrp];

        int j = 0;
        for (; j + 8 <= cnt; j += 8) {
            uint2 p[8];
            float wj[8];
#pragma unroll
            for (int u = 0; u < 8; u++) {
                float4 mt = mrow[j + u];
                wj[u] = h ? mt.z : mt.y;
                p[u] = g_xhh[(size_t)__float_as_int(mt.x) * 32 + lane];
            }
#pragma unroll
            for (int u = 0; u < 8; u++) {
                __half2 h01 = *reinterpret_cast<__half2*>(&p[u].x);
                __half2 h23 = *reinterpret_cast<__half2*>(&p[u].y);
                float2 f01 = __half22float2(h01);
                float2 f23 = __half22float2(h23);
                acc.x += wj[u] * f01.x; acc.y += wj[u] * f01.y;
                acc.z += wj[u] * f23.x; acc.w += wj[u] * f23.y;
            }
        }
        for (; j < cnt; j++) {
            float4 mt = mrow[j];
            float wj = h ? mt.z : mt.y;
            uint2 p = g_xhh[(size_t)__float_as_int(mt.x) * 32 + lane];
            __half2 h01 = *reinterpret_cast<__half2*>(&p.x);
            __half2 h23 = *reinterpret_cast<__half2*>(&p.y);
            float2 f01 = __half22float2(h01);
            float2 f23 = __half22float2(h23);
            acc.x += wj * f01.x; acc.y += wj * f01.y;
            acc.z += wj * f23.x; acc.w += wj * f23.y;
        }
        __syncwarp();
    }

#pragma unroll
    for (int off = 16; off; off >>= 1) {
        sum0 += __shfl_xor_sync(0xffffffffu, sum0, off);
        sum1 += __shfl_xor_sync(0xffffffffu, sum1, off);
    }
    const float inv = 1.0f / ((h ? sum1 : sum0) + 1e-16f);

    __half2 a01 = __floats2half2_rn(acc.x * inv, acc.y * inv);
    __half2 a23 = __floats2half2_rn(acc.z * inv, acc.w * inv);
    uint2 pk;
    pk.x = *reinterpret_cast<unsigned*>(&a01);
    pk.y = *reinterpret_cast<unsigned*>(&a23);
    g_agghh[(size_t)i * 32 + lane] = pk;
}

// ============ GEMM2 (wmma fp16): out = agg @ Wout + bias =====================
#define G2_A_STRIDE 136   // halfs per agg row (128 + 8 pad), 272B
#define G2_B_STRIDE 72    // halfs per Wout row (64 + 8 pad), 144B
#define G2_C_STRIDE 68    // floats per C row (64 + 4 pad), 272B
#define G2_A_BYTES  (64 * G2_A_STRIDE * 2)                  // 17408
#define G2_AB_BYTES (G2_A_BYTES + 128 * G2_B_STRIDE * 2)    // 35840

__global__ __launch_bounds__(256) void k_gemm_out(const float* __restrict__ Wout,
                                                  const float* __restrict__ bias,
                                                  float* __restrict__ out) {
    __shared__ __align__(16) char sm_raw[G2_AB_BYTES];
    __half (*AggS)[G2_A_STRIDE] = reinterpret_cast<__half(*)[G2_A_STRIDE]>(sm_raw);
    __half (*WtS)[G2_B_STRIDE]  = reinterpret_cast<__half(*)[G2_B_STRIDE]>(sm_raw + G2_A_BYTES);
    float  (*Cs)[G2_C_STRIDE]   = reinterpret_cast<float(*)[G2_C_STRIDE]>(sm_raw);

    const int tid = threadIdx.x;
    const int wid = tid >> 5;
    const int wr  = wid >> 2;     // 0..1 -> 32-row tile
    const int wc  = wid & 3;      // 0..3 -> 16-col tile
    const int row0 = blockIdx.x * 64;

#pragma unroll
    for (int it = 0; it < 8; it++) {
        int idx = tid + it * 256;            // 0..2047
        int r = idx >> 5, c = idx & 31;
        int grow = row0 + r;
        uint2 v = make_uint2(0u, 0u);
        if (grow < N_NODES) v = g_agghh[(size_t)grow * 32 + c];
        *(uint2*)&AggS[r][c * 4] = v;
    }
    const float4* W4 = (const float4*)Wout;
#pragma unroll
    for (int it = 0; it < 8; it++) {
        int idx = tid + it * 256;            // 0..2047 float4s
        int r = idx >> 4, c4 = idx & 15;     // r: 0..127, cols c4*4
        float4 f = W4[r * 16 + c4];
        __half2* dst = (__half2*)&WtS[r][c4 * 4];
        dst[0] = __floats2half2_rn(f.x, f.y);
        dst[1] = __floats2half2_rn(f.z, f.w);
    }
    __syncthreads();

    wmma::fragment<wmma::accumulator, 16, 16, 16, float> cfrag[2];
#pragma unroll
    for (int i = 0; i < 2; i++) wmma::fill_fragment(cfrag[i], 0.0f);

#pragma unroll
    for (int ks = 0; ks < 8; ks++) {
        wmma::fragment<wmma::matrix_a, 16, 16, 16, __half, wmma::row_major> afrag[2];
        wmma::fragment<wmma::matrix_b, 16, 16, 16, __half, wmma::row_major> bfrag;
#pragma unroll
        for (int i = 0; i < 2; i++)
            wmma::load_matrix_sync(afrag[i], &AggS[wr * 32 + i * 16][ks * 16], G2_A_STRIDE);
        wmma::load_matrix_sync(bfrag, &WtS[ks * 16][wc * 16], G2_B_STRIDE);
#pragma unroll
        for (int i = 0; i < 2; i++)
            wmma::mma_sync(cfrag[i], afrag[i], bfrag, cfrag[i]);
    }
    __syncthreads();   // done reading AggS; Cs aliases it
#pragma unroll
    for (int i = 0; i < 2; i++)
        wmma::store_matrix_sync(&Cs[wr * 32 + i * 16][wc * 16],
                                cfrag[i], G2_C_STRIDE, wmma::mem_row_major);
    __syncthreads();

    const int tn = tid & 15;
    const int tm = tid >> 4;
    float4 bv = ((const float4*)bias)[tn];
    float4* out4 = (float4*)out;
#pragma unroll
    for (int i = 0; i < 4; i++) {
        int row = tm * 4 + i;
        int grow = row0 + row;
        if (grow < N_NODES) {
            float4 v = *(float4*)&Cs[row][tn * 4];
            v.x += bv.x; v.y += bv.y; v.z += bv.z; v.w += bv.w;
            out4[(size_t)grow * (OUT_CH / 4) + tn] = v;
        }
    }
}

// ============================== launch ======================================
// Fork-join: GEMM1 runs on the capture stream while count->scan->scatter runs
// on a second stream; joined before k_aggregate. Streams/events are created
// lazily on the first (uncaptured) correctness call and reused during capture.
extern "C" void kernel_launch(void* const* d_in, const int* in_sizes, int n_in,
                              void* d_out, int out_size) {
    const float* x     = (const float*)d_in[0];
    const int*   ei    = (const int*)d_in[1];     // int32 edge_index
    const float* Wl    = (const float*)d_in[2];
    const float* att_l = (const float*)d_in[3];
    const float* att_r = (const float*)d_in[4];
    const float* Wout  = (const float*)d_in[5];
    const float* bias  = (const float*)d_in[6];
    float*       out   = (float*)d_out;

    (void)in_sizes; (void)n_in; (void)out_size;

    static cudaStream_t s2 = nullptr;
    static cudaEvent_t  ev_fork = nullptr, ev_join = nullptr;
    if (s2 == nullptr) {                       // first call is uncaptured
        cudaStreamCreateWithFlags(&s2, cudaStreamNonBlocking);
        cudaEventCreateWithFlags(&ev_fork, cudaEventDisableTiming);
        cudaEventCreateWithFlags(&ev_join, cudaEventDisableTiming);
    }

    cudaEventRecord(ev_fork, 0);               // fork from capture stream
    cudaStreamWaitEvent(s2, ev_fork, 0);

    // branch B (stream s2): CSR build
    k_count<<<COUNT_BLOCKS, 256, 0, s2>>>(ei);
    k_scan_a<<<SCAN_NB, SCAN_B, 0, s2>>>();
    k_scan_bc<<<SCAN_NB, SCAN_B, 0, s2>>>();
    k_scatter<<<(N_EDGES / 4 + N_NODES + 255) / 256, 256, 0, s2>>>(ei);
    cudaEventRecord(ev_join, s2);

    // branch A (capture stream): projection + attention dots
    k_gemm1<<<GEMM1_BLOCKS, 256>>>(x, Wl, att_l, att_r);

    // join, then the dependent tail
    cudaStreamWaitEvent(0, ev_join, 0);
    k_aggregate<<<(N_NODES * 32 + 255) / 256, 256>>>();
    k_gemm_out<<<(N_NODES + 63) / 64, 256>>>(Wout, bias, out);
}

// round 16
// speedup vs baseline: 1.0973x; 1.0222x over previous
#include <cuda_runtime.h>
#include <cuda_fp16.h>
#include <mma.h>
#include <cstdint>

using namespace nvcuda;

#define N_NODES 50000
#define N_EDGES 800000
#define E_TOT   (N_EDGES + N_NODES)   // 850000 (self-loops appended)
#define IN_CH   128
#define HC      128                    // HEADS*OUT_CH
#define HEADS   2
#define OUT_CH  64
#define NEG_SLOPE 0.2f

#define SCAN_B  256
#define SCAN_NB ((N_NODES + SCAN_B - 1) / SCAN_B)   // 196
#define GEMM1_BLOCKS ((N_NODES + 63) / 64)          // 782
#define COUNT_BLOCKS ((N_EDGES / 4 + 255) / 256)    // 782
#define SCATTER_BLOCKS ((N_EDGES / 4 + N_NODES + 255) / 256)   // 977

// ---------------- scratch (static device memory; no allocations) -------------
__device__ uint2  g_xhh[N_NODES * 32];          // fp16 xh  [N][64 x half2] (256B/row)
__device__ uint2  g_agghh[N_NODES * 32];        // fp16 agg [N][64 x half2] (256B/row)
__device__ float2 g_al2[N_NODES];               // (alpha_l h0, h1) per node
__device__ float2 g_ar2[N_NODES];               // (alpha_r h0, h1) per node
__device__ int    g_cnt[N_NODES];               // zero-init; delta counts (self-loop implicit)
__device__ int    g_ptr[N_NODES + 1];           // LOCAL-exclusive row offsets (per scan block)
__device__ int    g_ptrf[N_NODES + 1];          // FINAL CSR row pointers
__device__ int    g_rank[N_EDGES];              // per-edge rank within its dst
__device__ int    g_srcs[E_TOT];                // CSR: src node per slot
__device__ int    g_bsum[SCAN_NB];              // per-block scan totals

__device__ __forceinline__ float leaky(float v) {
    return v > 0.0f ? v : NEG_SLOPE * v;
}

// smem layout for GEMM1 role (A/B tiles aliased by the C staging buffer)
#define AS_STRIDE 72      // halfs per A row (64 + pad), 144B
#define BS_STRIDE 136     // halfs per B row (128 + pad), 272B
#define CS_STRIDE 132     // floats per C row (128 + pad), 528B
#define AS_BYTES  (64 * AS_STRIDE * 2)                 // 9216
#define AB_BYTES  (AS_BYTES + 64 * BS_STRIDE * 2)      // 26624
#define CS_BYTES  (64 * CS_STRIDE * 4)                 // 33792
#define SMEM_BYTES (CS_BYTES > AB_BYTES ? CS_BYTES : AB_BYTES)

// ========== MEGA1: [GEMM1(wmma fp16) blocks | edge-count blocks] =============
__global__ void k_mega1(const float* __restrict__ x,
                        const float* __restrict__ Wl,
                        const float* __restrict__ att_l,
                        const float* __restrict__ att_r,
                        const int*   __restrict__ ei) {
    __shared__ __align__(16) char smem_raw[SMEM_BYTES];

    const int tid = threadIdx.x;

    if (blockIdx.x >= GEMM1_BLOCKS) {
        // ---- histogram role: 4 edges/thread, record ranks ----
        int t = (blockIdx.x - GEMM1_BLOCKS) * 256 + tid;
        if (t < N_EDGES / 4) {
            int4 d = ((const int4*)(ei + N_EDGES))[t];
            int4 r = make_int4(0, 0, 0, 0);
            if ((unsigned)d.x < N_NODES) r.x = atomicAdd(&g_cnt[d.x], 1);
            if ((unsigned)d.y < N_NODES) r.y = atomicAdd(&g_cnt[d.y], 1);
            if ((unsigned)d.z < N_NODES) r.z = atomicAdd(&g_cnt[d.z], 1);
            if ((unsigned)d.w < N_NODES) r.w = atomicAdd(&g_cnt[d.w], 1);
            ((int4*)g_rank)[t] = r;
        }
        return;
    }

    // ---- GEMM role: xh = x @ Wl via wmma fp16 (fp32 accum) ----
    __half (*As)[AS_STRIDE] = reinterpret_cast<__half(*)[AS_STRIDE]>(smem_raw);
    __half (*Bs)[BS_STRIDE] = reinterpret_cast<__half(*)[BS_STRIDE]>(smem_raw + AS_BYTES);
    float  (*Cs)[CS_STRIDE] = reinterpret_cast<float(*)[CS_STRIDE]>(smem_raw);

    const int row0 = blockIdx.x * 64;
    const int wid  = tid >> 5;            // 0..7
    const int wr   = wid >> 2;            // 0..1 -> 32-row tile
    const int wc   = wid & 3;             // 0..3 -> 32-col tile

    wmma::fragment<wmma::accumulator, 16, 16, 16, float> cfrag[2][2];
#pragma unroll
    for (int i = 0; i < 2; i++)
#pragma unroll
        for (int j = 0; j < 2; j++) wmma::fill_fragment(cfrag[i][j], 0.0f);

    const float4* x4  = (const float4*)x;
    const float4* Wl4 = (const float4*)Wl;

    for (int k0 = 0; k0 < IN_CH; k0 += 64) {
        __syncthreads();
        {
            int r  = tid >> 2;
            int cs = (tid & 3) * 16;
            int grow = row0 + r;
            __half2* dst = (__half2*)&As[r][cs];
#pragma unroll
            for (int u = 0; u < 4; u++) {
                float4 f = make_float4(0.f, 0.f, 0.f, 0.f);
                if (grow < N_NODES)
                    f = x4[(size_t)grow * (IN_CH / 4) + (k0 + cs) / 4 + u];
                dst[2 * u]     = __floats2half2_rn(f.x, f.y);
                dst[2 * u + 1] = __floats2half2_rn(f.z, f.w);
            }
        }
        {
            int kr = tid >> 2;
            int bc = (tid & 3) * 32;
            __half2* dst = (__half2*)&Bs[kr][bc];
#pragma unroll
            for (int u = 0; u < 8; u++) {
                float4 f = Wl4[(size_t)(k0 + kr) * (HC / 4) + bc / 4 + u];
                dst[2 * u]     = __floats2half2_rn(f.x, f.y);
                dst[2 * u + 1] = __floats2half2_rn(f.z, f.w);
            }
        }
        __syncthreads();
#pragma unroll
        for (int ks = 0; ks < 4; ks++) {
            wmma::fragment<wmma::matrix_a, 16, 16, 16, __half, wmma::row_major> afrag[2];
            wmma::fragment<wmma::matrix_b, 16, 16, 16, __half, wmma::row_major> bfrag[2];
#pragma unroll
            for (int i = 0; i < 2; i++)
                wmma::load_matrix_sync(afrag[i], &As[wr * 32 + i * 16][ks * 16], AS_STRIDE);
#pragma unroll
            for (int j = 0; j < 2; j++)
                wmma::load_matrix_sync(bfrag[j], &Bs[ks * 16][wc * 32 + j * 16], BS_STRIDE);
#pragma unroll
            for (int i = 0; i < 2; i++)
#pragma unroll
                for (int j = 0; j < 2; j++)
                    wmma::mma_sync(cfrag[i][j], afrag[i], bfrag[j], cfrag[i][j]);
        }
    }
    __syncthreads();
#pragma unroll
    for (int i = 0; i < 2; i++)
#pragma unroll
        for (int j = 0; j < 2; j++)
            wmma::store_matrix_sync(&Cs[wr * 32 + i * 16][wc * 32 + j * 16],
                                    cfrag[i][j], CS_STRIDE, wmma::mem_row_major);
    __syncthreads();

    // epilogue: fp16 xh store + fused attention dots
    const int tn = tid & 31;
    const int tm = tid >> 5;
    float4 attl = ((const float4*)att_l)[tn];
    float4 attr = ((const float4*)att_r)[tn];
#pragma unroll
    for (int i = 0; i < 8; i++) {
        int row = tm * 8 + i;
        float4 v = *(float4*)&Cs[row][tn * 4];

        float pl = v.x * attl.x + v.y * attl.y + v.z * attl.z + v.w * attl.w;
        float pr = v.x * attr.x + v.y * attr.y + v.z * attr.z + v.w * attr.w;
#pragma unroll
        for (int off = 8; off; off >>= 1) {
            pl += __shfl_xor_sync(0xffffffffu, pl, off);
            pr += __shfl_xor_sync(0xffffffffu, pr, off);
        }
        float pl1 = __shfl_sync(0xffffffffu, pl, 16);
        float pr1 = __shfl_sync(0xffffffffu, pr, 16);

        int grow = row0 + row;
        if (grow < N_NODES) {
            __half2 h01 = __floats2half2_rn(v.x, v.y);
            __half2 h23 = __floats2half2_rn(v.z, v.w);
            uint2 pk;
            pk.x = *reinterpret_cast<unsigned*>(&h01);
            pk.y = *reinterpret_cast<unsigned*>(&h23);
            g_xhh[(size_t)grow * 32 + tn] = pk;
            if (tn == 0) {
                g_al2[grow] = make_float2(pl, pl1);
                g_ar2[grow] = make_float2(pr, pr1);
            }
        }
    }
}

// Phase A: per-block scan of (cnt+1); LOCAL exclusive into g_ptr, totals into
// g_bsum; resets cnt for the next graph replay.
__global__ void k_scan_a() {
    __shared__ int sm[SCAN_B];
    const int tid = threadIdx.x;
    const int idx = blockIdx.x * SCAN_B + tid;
    int v = 0;
    if (idx < N_NODES) {
        v = g_cnt[idx] + 1;      // +1 = self-loop (occupies LAST slot of row)
        g_cnt[idx] = 0;          // re-arm for next replay
    }
    sm[tid] = v;
    __syncthreads();
#pragma unroll
    for (int off = 1; off < SCAN_B; off <<= 1) {
        int t = 0;
        if (tid >= off) t = sm[tid - off];
        __syncthreads();
        sm[tid] += t;
        __syncthreads();
    }
    if (idx < N_NODES) g_ptr[idx] = sm[tid] - v;       // local exclusive
    if (tid == SCAN_B - 1) g_bsum[blockIdx.x] = sm[tid];
}

// ====== scatter (fused scan-BC): every block scans the 196 block sums in
// smem, then scatters with pos = local_ptr + sboff + rank. Blocks < SCAN_NB
// also materialize the FINAL pointers into g_ptrf for the aggregate. =========
__global__ void k_scatter(const int* __restrict__ ei) {
    __shared__ int sm[SCAN_B];        // inclusive scan workspace
    __shared__ int sboff[SCAN_B];     // exclusive block offsets
    const int tid = threadIdx.x;
    const int b   = blockIdx.x;

    int v = (tid < SCAN_NB) ? g_bsum[tid] : 0;
    sm[tid] = v;
    __syncthreads();
#pragma unroll
    for (int off = 1; off < SCAN_B; off <<= 1) {
        int t = 0;
        if (tid >= off) t = sm[tid - off];
        __syncthreads();
        sm[tid] += t;
        __syncthreads();
    }
    sboff[tid] = sm[tid] - v;                       // exclusive
    __syncthreads();
    const int total = sm[SCAN_NB - 1];              // == E_TOT

    // final pointers for the aggregate (blocks 0..SCAN_NB-1)
    if (b < SCAN_NB) {
        int idx = b * SCAN_B + tid;
        if (idx < N_NODES)
            g_ptrf[idx] = g_ptr[idx] + sboff[b];
        if (b == SCAN_NB - 1 && tid == 0)
            g_ptrf[N_NODES] = total;
    }

    // scatter phase
    const int NE4 = N_EDGES / 4;
    int t = b * SCAN_B + tid;
    if (t < NE4) {
        int4 s = ((const int4*)ei)[t];
        int4 d = ((const int4*)(ei + N_EDGES))[t];
        int4 r = ((const int4*)g_rank)[t];
        if ((unsigned)s.x < N_NODES && (unsigned)d.x < N_NODES)
            g_srcs[g_ptr[d.x] + sboff[d.x >> 8] + r.x] = s.x;
        if ((unsigned)s.y < N_NODES && (unsigned)d.y < N_NODES)
            g_srcs[g_ptr[d.y] + sboff[d.y >> 8] + r.y] = s.y;
        if ((unsigned)s.z < N_NODES && (unsigned)d.z < N_NODES)
            g_srcs[g_ptr[d.z] + sboff[d.z >> 8] + r.z] = s.z;
        if ((unsigned)s.w < N_NODES && (unsigned)d.w < N_NODES)
            g_srcs[g_ptr[d.w] + sboff[d.w >> 8] + r.w] = s.w;
    } else {
        int n = t - NE4;
        if (n < N_NODES) {
            // self-loop: last slot of row n = ptrf[n+1] - 1
            int pf = (n + 1 == N_NODES) ? total
                                        : g_ptr[n + 1] + sboff[(n + 1) >> 8];
            g_srcs[pf - 1] = n;
        }
    }
}

// ====== single-pass segment softmax + weighted gather (warp per node) ========
__global__ __launch_bounds__(256) void k_aggregate() {
    __shared__ float4 meta[8][32];       // (src, w0, w1, -) per in-flight edge
    const int wrp  = threadIdx.x >> 5;
    const int warp = (blockIdx.x * blockDim.x + threadIdx.x) >> 5;
    const int lane = threadIdx.x & 31;
    if (warp >= N_NODES) return;
    const int i = warp;
    const int start = g_ptrf[i], end = g_ptrf[i + 1];

    const float2 ar = g_ar2[i];
    const int h = (lane >= 16) ? 1 : 0;

    float sum0 = 0.f, sum1 = 0.f;        // per-lane weight totals
    float4 acc = make_float4(0.f, 0.f, 0.f, 0.f);

    for (int eb = start; eb < end; eb += 32) {
        int e = eb + lane;
        float w0 = 0.f, w1 = 0.f;
        int sm_ = 0;
        if (e < end) {
            sm_ = g_srcs[e];
            float2 al = g_al2[sm_];
            w0 = __expf(leaky(al.x + ar.x));
            w1 = __expf(leaky(al.y + ar.y));
            sum0 += w0;
            sum1 += w1;
        }
        meta[wrp][lane] = make_float4(__int_as_float(sm_), w0, w1, 0.f);
        __syncwarp();
        const int cnt = min(32, end - eb);
        const float4* mrow = meta[wrp];

        int j = 0;
        for (; j + 8 <= cnt; j += 8) {
            uint2 p[8];
            float wj[8];
#pragma unroll
            for (int u = 0; u < 8; u++) {
                float4 mt = mrow[j + u];
                wj[u] = h ? mt.z : mt.y;
                p[u] = g_xhh[(size_t)__float_as_int(mt.x) * 32 + lane];
            }
#pragma unroll
            for (int u = 0; u < 8; u++) {
                __half2 h01 = *reinterpret_cast<__half2*>(&p[u].x);
                __half2 h23 = *reinterpret_cast<__half2*>(&p[u].y);
                float2 f01 = __half22float2(h01);
                float2 f23 = __half22float2(h23);
                acc.x += wj[u] * f01.x; acc.y += wj[u] * f01.y;
                acc.z += wj[u] * f23.x; acc.w += wj[u] * f23.y;
            }
        }
        for (; j < cnt; j++) {
            float4 mt = mrow[j];
            float wj = h ? mt.z : mt.y;
            uint2 p = g_xhh[(size_t)__float_as_int(mt.x) * 32 + lane];
            __half2 h01 = *reinterpret_cast<__half2*>(&p.x);
            __half2 h23 = *reinterpret_cast<__half2*>(&p.y);
            float2 f01 = __half22float2(h01);
            float2 f23 = __half22float2(h23);
            acc.x += wj * f01.x; acc.y += wj * f01.y;
            acc.z += wj * f23.x; acc.w += wj * f23.y;
        }
        __syncwarp();
    }

#pragma unroll
    for (int off = 16; off; off >>= 1) {
        sum0 += __shfl_xor_sync(0xffffffffu, sum0, off);
        sum1 += __shfl_xor_sync(0xffffffffu, sum1, off);
    }
    const float inv = 1.0f / ((h ? sum1 : sum0) + 1e-16f);

    __half2 a01 = __floats2half2_rn(acc.x * inv, acc.y * inv);
    __half2 a23 = __floats2half2_rn(acc.z * inv, acc.w * inv);
    uint2 pk;
    pk.x = *reinterpret_cast<unsigned*>(&a01);
    pk.y = *reinterpret_cast<unsigned*>(&a23);
    g_agghh[(size_t)i * 32 + lane] = pk;
}

// ============ GEMM2 (wmma fp16): out = agg @ Wout + bias =====================
#define G2_A_STRIDE 136   // halfs per agg row (128 + 8 pad), 272B
#define G2_B_STRIDE 72    // halfs per Wout row (64 + 8 pad), 144B
#define G2_C_STRIDE 68    // floats per C row (64 + 4 pad), 272B
#define G2_A_BYTES  (64 * G2_A_STRIDE * 2)                  // 17408
#define G2_AB_BYTES (G2_A_BYTES + 128 * G2_B_STRIDE * 2)    // 35840

__global__ __launch_bounds__(256) void k_gemm_out(const float* __restrict__ Wout,
                                                  const float* __restrict__ bias,
                                                  float* __restrict__ out) {
    __shared__ __align__(16) char sm_raw[G2_AB_BYTES];
    __half (*AggS)[G2_A_STRIDE] = reinterpret_cast<__half(*)[G2_A_STRIDE]>(sm_raw);
    __half (*WtS)[G2_B_STRIDE]  = reinterpret_cast<__half(*)[G2_B_STRIDE]>(sm_raw + G2_A_BYTES);
    float  (*Cs)[G2_C_STRIDE]   = reinterpret_cast<float(*)[G2_C_STRIDE]>(sm_raw);

    const int tid = threadIdx.x;
    const int wid = tid >> 5;
    const int wr  = wid >> 2;     // 0..1 -> 32-row tile
    const int wc  = wid & 3;      // 0..3 -> 16-col tile
    const int row0 = blockIdx.x * 64;

#pragma unroll
    for (int it = 0; it < 8; it++) {
        int idx = tid + it * 256;            // 0..2047
        int r = idx >> 5, c = idx & 31;
        int grow = row0 + r;
        uint2 v = make_uint2(0u, 0u);
        if (grow < N_NODES) v = g_agghh[(size_t)grow * 32 + c];
        *(uint2*)&AggS[r][c * 4] = v;
    }
    const float4* W4 = (const float4*)Wout;
#pragma unroll
    for (int it = 0; it < 8; it++) {
        int idx = tid + it * 256;            // 0..2047 float4s
        int r = idx >> 4, c4 = idx & 15;     // r: 0..127, cols c4*4
        float4 f = W4[r * 16 + c4];
        __half2* dst = (__half2*)&WtS[r][c4 * 4];
        dst[0] = __floats2half2_rn(f.x, f.y);
        dst[1] = __floats2half2_rn(f.z, f.w);
    }
    __syncthreads();

    wmma::fragment<wmma::accumulator, 16, 16, 16, float> cfrag[2];
#pragma unroll
    for (int i = 0; i < 2; i++) wmma::fill_fragment(cfrag[i], 0.0f);

#pragma unroll
    for (int ks = 0; ks < 8; ks++) {
        wmma::fragment<wmma::matrix_a, 16, 16, 16, __half, wmma::row_major> afrag[2];
        wmma::fragment<wmma::matrix_b, 16, 16, 16, __half, wmma::row_major> bfrag;
#pragma unroll
        for (int i = 0; i < 2; i++)
            wmma::load_matrix_sync(afrag[i], &AggS[wr * 32 + i * 16][ks * 16], G2_A_STRIDE);
        wmma::load_matrix_sync(bfrag, &WtS[ks * 16][wc * 16], G2_B_STRIDE);
#pragma unroll
        for (int i = 0; i < 2; i++)
            wmma::mma_sync(cfrag[i], afrag[i], bfrag, cfrag[i]);
    }
    __syncthreads();   // done reading AggS; Cs aliases it
#pragma unroll
    for (int i = 0; i < 2; i++)
        wmma::store_matrix_sync(&Cs[wr * 32 + i * 16][wc * 16],
                                cfrag[i], G2_C_STRIDE, wmma::mem_row_major);
    __syncthreads();

    const int tn = tid & 15;
    const int tm = tid >> 4;
    float4 bv = ((const float4*)bias)[tn];
    float4* out4 = (float4*)out;
#pragma unroll
    for (int i = 0; i < 4; i++) {
        int row = tm * 4 + i;
        int grow = row0 + row;
        if (grow < N_NODES) {
            float4 v = *(float4*)&Cs[row][tn * 4];
            v.x += bv.x; v.y += bv.y; v.z += bv.z; v.w += bv.w;
            out4[(size_t)grow * (OUT_CH / 4) + tn] = v;
        }
    }
}

// ============================== launch ======================================
extern "C" void kernel_launch(void* const* d_in, const int* in_sizes, int n_in,
                              void* d_out, int out_size) {
    const float* x     = (const float*)d_in[0];
    const int*   ei    = (const int*)d_in[1];     // int32 edge_index
    const float* Wl    = (const float*)d_in[2];
    const float* att_l = (const float*)d_in[3];
    const float* att_r = (const float*)d_in[4];
    const float* Wout  = (const float*)d_in[5];
    const float* bias  = (const float*)d_in[6];
    float*       out   = (float*)d_out;

    (void)in_sizes; (void)n_in; (void)out_size;

    k_mega1<<<GEMM1_BLOCKS + COUNT_BLOCKS, 256>>>(x, Wl, att_l, att_r, ei);
    k_scan_a<<<SCAN_NB, SCAN_B>>>();
    k_scatter<<<SCATTER_BLOCKS, SCAN_B>>>(ei);
    k_aggregate<<<(N_NODES * 32 + 255) / 256, 256>>>();
    k_gemm_out<<<(N_NODES + 63) / 64, 256>>>(Wout, bias, out);
}